// round 6
// baseline (speedup 1.0000x reference)
#include <cuda_runtime.h>
#include <cstdint>

#define T_STEPS 12
#define BATCH   64
#define NODE    207
#define HID     16
#define HDIM    6624          // NODE*HID*2
#define IN_DIM  16560         // NODE*HID*5
#define X_DIM   3312          // NODE*HID
#define WSTRIDE 6656          // padded row stride (1664 float4)
#define NB      138           // persistent grid: 138 blocks * 48 rows = 6624
#define ROWS_PB 48
#define CSM4    256           // smem-cached float4 per row   (cols [0,1024))
// f4 ranges: tier1 [0,256) smem, tier2 [256,768) L2-resident, tier3 [768,1664) streamed
#define SMEM_FLOATS (WSTRIDE + ROWS_PB * CSM4 * 4)
#define SMEM_BYTES  (SMEM_FLOATS * 4)

// Scratch (device globals: allocation-free rule)
__device__ float  g_hz[BATCH * HDIM];
__device__ float  g_inpT[IN_DIM * BATCH];   // (16560, 64)
__device__ float  g_pre[BATCH * HDIM];
__device__ float  g_w[HDIM * WSTRIDE];      // padded fp32 W_hh (~176 MB)
__device__ unsigned g_bar[2];               // [0]=count (monotone), [1]=phase

// ---------------------------------------------------------------------------
__global__ __launch_bounds__(256) void kH(const float* __restrict__ W)
{
    const int o = blockIdx.x;
    for (int i = threadIdx.x; i < WSTRIDE; i += 256)
        g_w[(size_t)o * WSTRIDE + i] = (i < HDIM) ? W[(size_t)o * HDIM + i] : 0.f;
}

// ---------------------------------------------------------------------------
// Kernel A: build inpT[:, b] directly (transposed layout, scattered writes).
// ---------------------------------------------------------------------------
__global__ __launch_bounds__(256) void kA(
    const float* __restrict__ hz, const float* __restrict__ sv_t,
    const float* __restrict__ Wf, const float* __restrict__ bf,
    const float* __restrict__ Wg, const float* __restrict__ bg,
    const float* __restrict__ conv_w, float* __restrict__ inpT)
{
    const int blk = blockIdx.x;
    const int b = blk / NODE;
    const int n = blk % NODE;
    const int tid = threadIdx.x;

    __shared__ float sh[HID], sz[HID], sf[HID * 2], sg[HID * HID];

    if (tid < 32) {
        float v = hz[b * HDIM + n * 32 + tid];
        if (tid & 1) sz[tid >> 1] = v;
        else         sh[tid >> 1] = v;
    }
    __syncthreads();

    {
        float acc = bg[tid];
#pragma unroll
        for (int l = 0; l < HID; l++) acc += sz[l] * Wg[l * 256 + tid];
        sg[tid] = tanhf(acc);
    }
    if (tid < 32) {
        float acc = bf[tid];
#pragma unroll
        for (int i = 0; i < HID; i++) acc += sh[i] * Wf[i * 32 + tid];
        sf[tid] = tanhf(acc);
    }
    __syncthreads();

    if (tid < 32) {
        const int i = tid >> 1, c = tid & 1;
        float acc = 0.f;
#pragma unroll
        for (int j = 0; j < HID; j++) acc += sg[i * HID + j] * sf[j * 2 + c];
        const int base = X_DIM + n * 64 + i * 4 + c * 2;   // row index in inpT
        inpT[(size_t)base * BATCH + b]       = sf[i * 2 + c];
        inpT[(size_t)(base + 1) * BATCH + b] = acc;
    }
    if (tid < HID) {
        float v = sv_t[(b * NODE + n) * 2 + 1];
        inpT[(size_t)(tid * NODE + n) * BATCH + b] = conv_w[tid] * v;
    }
}

// ---------------------------------------------------------------------------
// Kernel B: Wih streamed evict-first (protect L2-resident W_hh columns).
// ---------------------------------------------------------------------------
__global__ __launch_bounds__(256) void kB(
    const float* __restrict__ inpT, const float* __restrict__ Wih,
    const float* __restrict__ bih, float* __restrict__ pre)
{
    const int tid = threadIdx.x;
    const int b  = tid & 63;
    const int jg = tid >> 6;
    const int o0 = blockIdx.x * 16 + jg * 4;

    const float* w0 = Wih + (size_t)o0 * IN_DIM;

    float acc[4];
#pragma unroll
    for (int k = 0; k < 4; k++) acc[k] = 0.f;

    for (int i = 0; i < IN_DIM; i += 4) {
        const float x0 = inpT[(size_t)(i    ) * BATCH + b];
        const float x1 = inpT[(size_t)(i + 1) * BATCH + b];
        const float x2 = inpT[(size_t)(i + 2) * BATCH + b];
        const float x3 = inpT[(size_t)(i + 3) * BATCH + b];
#pragma unroll
        for (int k = 0; k < 4; k++) {
            const float4 w = __ldcs(reinterpret_cast<const float4*>(
                                        w0 + (size_t)k * IN_DIM + i));
            acc[k] += w.x * x0 + w.y * x1 + w.z * x2 + w.w * x3;
        }
    }
#pragma unroll
    for (int k = 0; k < 4; k++)
        pre[b * HDIM + o0 + k] = acc[k] + bih[o0 + k];
}

// ---------------------------------------------------------------------------
// Kernel C (persistent, fp32, 3-tier W, INTERLEAVED issue):
// 138 blocks x 512 threads, 1 CTA/SM, ~223 KB dynamic smem.
// Single 28-iteration loop per step: every iter issues a streamed (DRAM)
// slot; iters 0..15 also an L2 slot; iters 0..7 also an smem slot. This
// keeps DRAM and LTS traffic concurrent within each warp.
// ---------------------------------------------------------------------------
extern __shared__ float s_dyn[];

__global__ __launch_bounds__(512, 1) void kC_persist(
    const float* __restrict__ W, const float* __restrict__ pre,
    const float* __restrict__ bhh, float* __restrict__ hz, int t)
{
    float* sh = s_dyn;                 // [0, WSTRIDE)
    float* wc = s_dyn + WSTRIDE;       // 48 rows * 1024 floats
    const int tid  = threadIdx.x;
    const int warp = tid >> 5;
    const int lane = tid & 31;
    const int rbase = blockIdx.x * ROWS_PB + warp * 3;

    const float4* H4 = reinterpret_cast<const float4*>(sh);
    const float4* W0 = reinterpret_cast<const float4*>(W + (size_t)(rbase    ) * WSTRIDE);
    const float4* W1 = reinterpret_cast<const float4*>(W + (size_t)(rbase + 1) * WSTRIDE);
    const float4* W2 = reinterpret_cast<const float4*>(W + (size_t)(rbase + 2) * WSTRIDE);
    const float4* C0 = reinterpret_cast<const float4*>(wc + (size_t)(warp * 3    ) * (CSM4 * 4));
    const float4* C1 = reinterpret_cast<const float4*>(wc + (size_t)(warp * 3 + 1) * (CSM4 * 4));
    const float4* C2 = reinterpret_cast<const float4*>(wc + (size_t)(warp * 3 + 2) * (CSM4 * 4));

    // fill smem W cache once per launch
#pragma unroll
    for (int r = 0; r < 3; r++) {
        const float4* src = reinterpret_cast<const float4*>(
            W + (size_t)(rbase + r) * WSTRIDE);
        float4* dst = reinterpret_cast<float4*>(
            wc + (size_t)(warp * 3 + r) * (CSM4 * 4));
        for (int k = lane; k < CSM4; k += 32) dst[k] = src[k];
    }
    if (tid < WSTRIDE - HDIM) sh[HDIM + tid] = 0.f;
    __syncthreads();

    for (int step = 0; step < BATCH; step++) {
        float a0 = 0.f, a1 = 0.f, a2 = 0.f;

        if (step > 0) {
            const float* hp = hz + (size_t)(step - 1) * HDIM;
            for (int i = tid; i < HDIM; i += 512) sh[i] = __ldcg(hp + i);
            __syncthreads();

#pragma unroll 1
            for (int i = 0; i < 28; i++) {
                // streamed slot (DRAM, evict-first): f4 cols [768,1664)
                {
                    const int k = 768 + i * 32 + lane;
                    const float4 wa = __ldcs(&W0[k]);
                    const float4 wb = __ldcs(&W1[k]);
                    const float4 wcv = __ldcs(&W2[k]);
                    const float4 h  = H4[k];
                    a0 += wa.x*h.x + wa.y*h.y + wa.z*h.z + wa.w*h.w;
                    a1 += wb.x*h.x + wb.y*h.y + wb.z*h.z + wb.w*h.w;
                    a2 += wcv.x*h.x + wcv.y*h.y + wcv.z*h.z + wcv.w*h.w;
                }
                // L2-resident slot: f4 cols [256,768)
                if (i < 16) {
                    const int k = 256 + i * 32 + lane;
                    const float4 wa = W0[k];
                    const float4 wb = W1[k];
                    const float4 wcv = W2[k];
                    const float4 h  = H4[k];
                    a0 += wa.x*h.x + wa.y*h.y + wa.z*h.z + wa.w*h.w;
                    a1 += wb.x*h.x + wb.y*h.y + wb.z*h.z + wb.w*h.w;
                    a2 += wcv.x*h.x + wcv.y*h.y + wcv.z*h.z + wcv.w*h.w;
                }
                // smem slot: f4 cols [0,256)
                if (i < 8) {
                    const int k = i * 32 + lane;
                    const float4 wa = C0[k];
                    const float4 wb = C1[k];
                    const float4 wcv = C2[k];
                    const float4 h  = H4[k];
                    a0 += wa.x*h.x + wa.y*h.y + wa.z*h.z + wa.w*h.w;
                    a1 += wb.x*h.x + wb.y*h.y + wb.z*h.z + wb.w*h.w;
                    a2 += wcv.x*h.x + wcv.y*h.y + wcv.z*h.z + wcv.w*h.w;
                }
            }
        }

#pragma unroll
        for (int s = 16; s; s >>= 1) {
            a0 += __shfl_xor_sync(0xffffffffu, a0, s);
            a1 += __shfl_xor_sync(0xffffffffu, a1, s);
            a2 += __shfl_xor_sync(0xffffffffu, a2, s);
        }
        if (lane == 0) {
            const float* pre_b = pre + (size_t)step * HDIM;
            float* hout = hz + (size_t)step * HDIM;
            __stcg(hout + rbase    , tanhf(a0 + pre_b[rbase    ] + bhh[rbase    ]));
            __stcg(hout + rbase + 1, tanhf(a1 + pre_b[rbase + 1] + bhh[rbase + 1]));
            __stcg(hout + rbase + 2, tanhf(a2 + pre_b[rbase + 2] + bhh[rbase + 2]));
        }

        // grid barrier (also protects smem h WAR for next step's staging)
        __threadfence();
        __syncthreads();
        if (tid == 0) {
            const unsigned k = (unsigned)(t * BATCH + step + 1);
            const unsigned old = atomicAdd(&g_bar[0], 1u);
            if (old == k * NB - 1u) {
                atomicExch(&g_bar[1], k);
            } else {
                while (atomicAdd(&g_bar[1], 0u) < k) __nanosleep(64);
            }
        }
        __syncthreads();
    }
}

// ---------------------------------------------------------------------------
extern "C" void kernel_launch(void* const* d_in, const int* in_sizes, int n_in,
                              void* d_out, int out_size)
{
    const float* sv    = (const float*)d_in[0];
    const float* init0 = (const float*)d_in[1];
    const float* Wf    = (const float*)d_in[2];
    const float* bf    = (const float*)d_in[3];
    const float* Wg    = (const float*)d_in[4];
    const float* bg    = (const float*)d_in[5];
    const float* cw    = (const float*)d_in[6];
    const float* Wih   = (const float*)d_in[7];
    const float* bih   = (const float*)d_in[8];
    const float* Whh   = (const float*)d_in[9];
    const float* bhh   = (const float*)d_in[10];

    float *hz, *inpT, *pre, *wpad;
    unsigned* bar;
    cudaGetSymbolAddress((void**)&hz,   g_hz);
    cudaGetSymbolAddress((void**)&inpT, g_inpT);
    cudaGetSymbolAddress((void**)&pre,  g_pre);
    cudaGetSymbolAddress((void**)&wpad, g_w);
    cudaGetSymbolAddress((void**)&bar,  g_bar);

    static int smem_set = 0;
    if (!smem_set) {
        cudaFuncSetAttribute(kC_persist,
                             cudaFuncAttributeMaxDynamicSharedMemorySize,
                             SMEM_BYTES);
        smem_set = 1;
    }

    // Launch order matters for ncu (-s 5): memset, kH, memcpy, kA, kB, kC -> kC profiled
    cudaMemsetAsync(bar, 0, 2 * sizeof(unsigned));
    kH<<<HDIM, 256>>>(Whh);
    cudaMemcpyAsync(hz, init0, (size_t)BATCH * HDIM * sizeof(float),
                    cudaMemcpyDeviceToDevice);

    for (int t = 0; t < T_STEPS; t++) {
        kA<<<BATCH * NODE, 256>>>(hz, sv + (size_t)t * BATCH * NODE * 2,
                                  Wf, bf, Wg, bg, cw, inpT);
        kB<<<HDIM / 16, 256>>>(inpT, Wih, bih, pre);
        kC_persist<<<NB, 512, SMEM_BYTES>>>(wpad, pre, bhh, hz, t);
    }

    cudaMemcpyAsync(d_out, hz, (size_t)BATCH * HDIM * sizeof(float),
                    cudaMemcpyDeviceToDevice);
}

// round 7
// speedup vs baseline: 1.3760x; 1.3760x over previous
#include <cuda_runtime.h>
#include <cstdint>

#define T_STEPS 12
#define BATCH   64
#define NODE    207
#define HID     16
#define HDIM    6624          // NODE*HID*2
#define IN_DIM  16560         // NODE*HID*5
#define X_DIM   3312          // NODE*HID
#define WSTRIDE 6656          // padded row stride (1664 float4)
#define NB      276           // persistent grid: 276 blocks * 24 rows = 6624
#define ROWS_PB 24
#define CSM4    128           // smem-cached float4 per row   (f4 cols [0,128))
// f4 ranges: tier1 [0,128) smem, tier2 [128,640) L2-resident, tier3 [640,1664) streamed
#define SMEM_FLOATS (WSTRIDE + ROWS_PB * CSM4 * 4)   // 6656 + 12288 = 18944
#define SMEM_BYTES  (SMEM_FLOATS * 4)                // 75.8 KB -> 2 CTAs/SM

// Scratch (device globals: allocation-free rule)
__device__ float  g_hz[BATCH * HDIM];
__device__ float  g_inpT[IN_DIM * BATCH];   // (16560, 64)
__device__ float  g_pre[BATCH * HDIM];
__device__ float  g_w[HDIM * WSTRIDE];      // padded fp32 W_hh (~176 MB)
__device__ unsigned g_bar[2];               // [0]=count (monotone), [1]=phase

// ---------------------------------------------------------------------------
__global__ __launch_bounds__(256) void kH(const float* __restrict__ W)
{
    const int o = blockIdx.x;
    for (int i = threadIdx.x; i < WSTRIDE; i += 256)
        g_w[(size_t)o * WSTRIDE + i] = (i < HDIM) ? W[(size_t)o * HDIM + i] : 0.f;
}

// ---------------------------------------------------------------------------
// Kernel A: build inpT[:, b] directly (transposed layout).
// ---------------------------------------------------------------------------
__global__ __launch_bounds__(256) void kA(
    const float* __restrict__ hz, const float* __restrict__ sv_t,
    const float* __restrict__ Wf, const float* __restrict__ bf,
    const float* __restrict__ Wg, const float* __restrict__ bg,
    const float* __restrict__ conv_w, float* __restrict__ inpT)
{
    const int blk = blockIdx.x;
    const int b = blk / NODE;
    const int n = blk % NODE;
    const int tid = threadIdx.x;

    __shared__ float sh[HID], sz[HID], sf[HID * 2], sg[HID * HID];

    if (tid < 32) {
        float v = hz[b * HDIM + n * 32 + tid];
        if (tid & 1) sz[tid >> 1] = v;
        else         sh[tid >> 1] = v;
    }
    __syncthreads();

    {
        float acc = bg[tid];
#pragma unroll
        for (int l = 0; l < HID; l++) acc += sz[l] * Wg[l * 256 + tid];
        sg[tid] = tanhf(acc);
    }
    if (tid < 32) {
        float acc = bf[tid];
#pragma unroll
        for (int i = 0; i < HID; i++) acc += sh[i] * Wf[i * 32 + tid];
        sf[tid] = tanhf(acc);
    }
    __syncthreads();

    if (tid < 32) {
        const int i = tid >> 1, c = tid & 1;
        float acc = 0.f;
#pragma unroll
        for (int j = 0; j < HID; j++) acc += sg[i * HID + j] * sf[j * 2 + c];
        const int base = X_DIM + n * 64 + i * 4 + c * 2;   // row index in inpT
        inpT[(size_t)base * BATCH + b]       = sf[i * 2 + c];
        inpT[(size_t)(base + 1) * BATCH + b] = acc;
    }
    if (tid < HID) {
        float v = sv_t[(b * NODE + n) * 2 + 1];
        inpT[(size_t)(tid * NODE + n) * BATCH + b] = conv_w[tid] * v;
    }
}

// ---------------------------------------------------------------------------
// Kernel B: Wih streamed evict-first (protect L2-resident W_hh columns).
// ---------------------------------------------------------------------------
__global__ __launch_bounds__(256) void kB(
    const float* __restrict__ inpT, const float* __restrict__ Wih,
    const float* __restrict__ bih, float* __restrict__ pre)
{
    const int tid = threadIdx.x;
    const int b  = tid & 63;
    const int jg = tid >> 6;
    const int o0 = blockIdx.x * 16 + jg * 4;

    const float* w0 = Wih + (size_t)o0 * IN_DIM;

    float acc[4];
#pragma unroll
    for (int k = 0; k < 4; k++) acc[k] = 0.f;

    for (int i = 0; i < IN_DIM; i += 4) {
        const float x0 = inpT[(size_t)(i    ) * BATCH + b];
        const float x1 = inpT[(size_t)(i + 1) * BATCH + b];
        const float x2 = inpT[(size_t)(i + 2) * BATCH + b];
        const float x3 = inpT[(size_t)(i + 3) * BATCH + b];
#pragma unroll
        for (int k = 0; k < 4; k++) {
            const float4 w = __ldcs(reinterpret_cast<const float4*>(
                                        w0 + (size_t)k * IN_DIM + i));
            acc[k] += w.x * x0 + w.y * x1 + w.z * x2 + w.w * x3;
        }
    }
#pragma unroll
    for (int k = 0; k < 4; k++)
        pre[b * HDIM + o0 + k] = acc[k] + bih[o0 + k];
}

// ---------------------------------------------------------------------------
// Kernel C (persistent, fp32, 3-tier W, phase-serial, x4 unroll):
// 276 blocks x 256 threads, 2 CTAs/SM (32 warps/SM, occ 50%).
// Per block: 24 static rows, 8 warps x 3 rows.
// Tier 3 first: f4 [640,1664) streamed __ldcs, x4 unroll (12 LDG in flight).
// Tier 2:       f4 [128,640)  default loads (L2-resident, 54 MB).
// Tier 1:       f4 [0,128)    smem-cached (12.9 MB chip-wide).
// ---------------------------------------------------------------------------
extern __shared__ float s_dyn[];

__global__ __launch_bounds__(256, 2) void kC_persist(
    const float* __restrict__ W, const float* __restrict__ pre,
    const float* __restrict__ bhh, float* __restrict__ hz, int t)
{
    float* sh = s_dyn;                 // [0, WSTRIDE)
    float* wc = s_dyn + WSTRIDE;       // 24 rows * 512 floats
    const int tid  = threadIdx.x;
    const int warp = tid >> 5;
    const int lane = tid & 31;
    const int rbase = blockIdx.x * ROWS_PB + warp * 3;

    const float4* H4 = reinterpret_cast<const float4*>(sh);
    const float4* W0 = reinterpret_cast<const float4*>(W + (size_t)(rbase    ) * WSTRIDE);
    const float4* W1 = reinterpret_cast<const float4*>(W + (size_t)(rbase + 1) * WSTRIDE);
    const float4* W2 = reinterpret_cast<const float4*>(W + (size_t)(rbase + 2) * WSTRIDE);
    const float4* C0 = reinterpret_cast<const float4*>(wc + (size_t)(warp * 3    ) * (CSM4 * 4));
    const float4* C1 = reinterpret_cast<const float4*>(wc + (size_t)(warp * 3 + 1) * (CSM4 * 4));
    const float4* C2 = reinterpret_cast<const float4*>(wc + (size_t)(warp * 3 + 2) * (CSM4 * 4));

    // fill smem W cache once per launch (each warp its own 3 rows)
#pragma unroll
    for (int r = 0; r < 3; r++) {
        const float4* src = reinterpret_cast<const float4*>(
            W + (size_t)(rbase + r) * WSTRIDE);
        float4* dst = reinterpret_cast<float4*>(
            wc + (size_t)(warp * 3 + r) * (CSM4 * 4));
        for (int k = lane; k < CSM4; k += 32) dst[k] = src[k];
    }
    if (tid < WSTRIDE - HDIM) sh[HDIM + tid] = 0.f;   // zero smem h pad
    __syncthreads();

    for (int step = 0; step < BATCH; step++) {
        float a0 = 0.f, a1 = 0.f, a2 = 0.f;

        if (step > 0) {
            const float* hp = hz + (size_t)(step - 1) * HDIM;
            for (int i = tid; i < HDIM; i += 256) sh[i] = __ldcg(hp + i);
            __syncthreads();

            // Tier 3 first: streamed f4 [640,1664), 32 lane-strided iters, x4
#pragma unroll 1
            for (int c = 0; c < 32; c += 4) {
                float4 wa[4], wb[4], wcc[4], hh[4];
#pragma unroll
                for (int j = 0; j < 4; j++) {
                    const int k = 640 + (c + j) * 32 + lane;
                    wa[j]  = __ldcs(&W0[k]);
                    wb[j]  = __ldcs(&W1[k]);
                    wcc[j] = __ldcs(&W2[k]);
                }
#pragma unroll
                for (int j = 0; j < 4; j++) {
                    const int k = 640 + (c + j) * 32 + lane;
                    hh[j] = H4[k];
                }
#pragma unroll
                for (int j = 0; j < 4; j++) {
                    a0 += wa[j].x*hh[j].x + wa[j].y*hh[j].y + wa[j].z*hh[j].z + wa[j].w*hh[j].w;
                    a1 += wb[j].x*hh[j].x + wb[j].y*hh[j].y + wb[j].z*hh[j].z + wb[j].w*hh[j].w;
                    a2 += wcc[j].x*hh[j].x + wcc[j].y*hh[j].y + wcc[j].z*hh[j].z + wcc[j].w*hh[j].w;
                }
            }
            // Tier 2: L2-resident f4 [128,640), 16 iters, x4
#pragma unroll 1
            for (int c = 0; c < 16; c += 4) {
                float4 wa[4], wb[4], wcc[4], hh[4];
#pragma unroll
                for (int j = 0; j < 4; j++) {
                    const int k = 128 + (c + j) * 32 + lane;
                    wa[j]  = W0[k];
                    wb[j]  = W1[k];
                    wcc[j] = W2[k];
                }
#pragma unroll
                for (int j = 0; j < 4; j++) {
                    const int k = 128 + (c + j) * 32 + lane;
                    hh[j] = H4[k];
                }
#pragma unroll
                for (int j = 0; j < 4; j++) {
                    a0 += wa[j].x*hh[j].x + wa[j].y*hh[j].y + wa[j].z*hh[j].z + wa[j].w*hh[j].w;
                    a1 += wb[j].x*hh[j].x + wb[j].y*hh[j].y + wb[j].z*hh[j].z + wb[j].w*hh[j].w;
                    a2 += wcc[j].x*hh[j].x + wcc[j].y*hh[j].y + wcc[j].z*hh[j].z + wcc[j].w*hh[j].w;
                }
            }
            // Tier 1: smem f4 [0,128), 4 iters
#pragma unroll
            for (int c = 0; c < 4; c++) {
                const int k = c * 32 + lane;
                const float4 wa = C0[k];
                const float4 wb = C1[k];
                const float4 wcc = C2[k];
                const float4 h  = H4[k];
                a0 += wa.x*h.x + wa.y*h.y + wa.z*h.z + wa.w*h.w;
                a1 += wb.x*h.x + wb.y*h.y + wb.z*h.z + wb.w*h.w;
                a2 += wcc.x*h.x + wcc.y*h.y + wcc.z*h.z + wcc.w*h.w;
            }
        }

#pragma unroll
        for (int s = 16; s; s >>= 1) {
            a0 += __shfl_xor_sync(0xffffffffu, a0, s);
            a1 += __shfl_xor_sync(0xffffffffu, a1, s);
            a2 += __shfl_xor_sync(0xffffffffu, a2, s);
        }
        if (lane == 0) {
            const float* pre_b = pre + (size_t)step * HDIM;
            float* hout = hz + (size_t)step * HDIM;
            __stcg(hout + rbase    , tanhf(a0 + pre_b[rbase    ] + bhh[rbase    ]));
            __stcg(hout + rbase + 1, tanhf(a1 + pre_b[rbase + 1] + bhh[rbase + 1]));
            __stcg(hout + rbase + 2, tanhf(a2 + pre_b[rbase + 2] + bhh[rbase + 2]));
        }

        // grid barrier (also protects smem h WAR for next step's staging)
        __threadfence();
        __syncthreads();
        if (tid == 0) {
            const unsigned k = (unsigned)(t * BATCH + step + 1);
            const unsigned old = atomicAdd(&g_bar[0], 1u);
            if (old == k * NB - 1u) {
                atomicExch(&g_bar[1], k);
            } else {
                while (atomicAdd(&g_bar[1], 0u) < k) __nanosleep(64);
            }
        }
        __syncthreads();
    }
}

// ---------------------------------------------------------------------------
extern "C" void kernel_launch(void* const* d_in, const int* in_sizes, int n_in,
                              void* d_out, int out_size)
{
    const float* sv    = (const float*)d_in[0];
    const float* init0 = (const float*)d_in[1];
    const float* Wf    = (const float*)d_in[2];
    const float* bf    = (const float*)d_in[3];
    const float* Wg    = (const float*)d_in[4];
    const float* bg    = (const float*)d_in[5];
    const float* cw    = (const float*)d_in[6];
    const float* Wih   = (const float*)d_in[7];
    const float* bih   = (const float*)d_in[8];
    const float* Whh   = (const float*)d_in[9];
    const float* bhh   = (const float*)d_in[10];

    float *hz, *inpT, *pre, *wpad;
    unsigned* bar;
    cudaGetSymbolAddress((void**)&hz,   g_hz);
    cudaGetSymbolAddress((void**)&inpT, g_inpT);
    cudaGetSymbolAddress((void**)&pre,  g_pre);
    cudaGetSymbolAddress((void**)&wpad, g_w);
    cudaGetSymbolAddress((void**)&bar,  g_bar);

    static int smem_set = 0;
    if (!smem_set) {
        cudaFuncSetAttribute(kC_persist,
                             cudaFuncAttributeMaxDynamicSharedMemorySize,
                             SMEM_BYTES);
        smem_set = 1;
    }

    // Launch order: memset, kH, memcpy, kA, kB, kC -> kC is profiled op #5
    cudaMemsetAsync(bar, 0, 2 * sizeof(unsigned));
    kH<<<HDIM, 256>>>(Whh);
    cudaMemcpyAsync(hz, init0, (size_t)BATCH * HDIM * sizeof(float),
                    cudaMemcpyDeviceToDevice);

    for (int t = 0; t < T_STEPS; t++) {
        kA<<<BATCH * NODE, 256>>>(hz, sv + (size_t)t * BATCH * NODE * 2,
                                  Wf, bf, Wg, bg, cw, inpT);
        kB<<<HDIM / 16, 256>>>(inpT, Wih, bih, pre);
        kC_persist<<<NB, 256, SMEM_BYTES>>>(wpad, pre, bhh, hz, t);
    }

    cudaMemcpyAsync(d_out, hz, (size_t)BATCH * HDIM * sizeof(float),
                    cudaMemcpyDeviceToDevice);
}